// round 9
// baseline (speedup 1.0000x reference)
#include <cuda_runtime.h>
#include <math.h>

#define HH 1024
#define WW 1024
#define NPIX (HH * WW)
#define N_ITERS 100

#define NBLK 256            // persistent blocks (guaranteed co-resident: 2/SM * 148+ SMs)
#define NTHR 512            // threads per block
#define RPB  4              // rows per block (256*4 = 1024)
#define SMEM_BYTES (RPB * WW * 16)   // 64 KB of packed weights

// ---------------- device scratch (statically allocated, ~36 MB) ----------------
__device__ uint4  g_wq[NPIX];       // 8x unorm16 weights per pixel (16B)
__device__ float  g_Y[NPIX];        // luminance plane
__device__ unsigned char g_mask[NPIX];
__device__ float2 g_x0[NPIX];       // ping
__device__ float2 g_x1[NPIX];       // pong
__device__ unsigned int g_bar_count;
__device__ volatile unsigned int g_bar_phase;

// ---------------- setup ----------------
__global__ void setup_kernel(const float* __restrict__ gray,
                             const float* __restrict__ app) {
    int pix = blockIdx.x * blockDim.x + threadIdx.x;
    if (pix >= NPIX) return;
    if (pix == 0) { g_bar_count = 0; g_bar_phase = 0; }   // reset barrier each launch

    float g0 = gray[3*pix+0], g1 = gray[3*pix+1], g2 = gray[3*pix+2];
    float a0 = app [3*pix+0], a1 = app [3*pix+1], a2 = app [3*pix+2];

    const float inv255 = 1.0f / 255.0f;
    float diff = (fabsf(g0-a0) + fabsf(g1-a1) + fabsf(g2-a2)) * inv255;
    bool colored = diff > 0.01f;

    float Y = (0.3f*g0 + 0.59f*g1 + 0.11f*g2) * inv255;

    float ya = (0.3f*a0 + 0.59f*a1 + 0.11f*a2) * inv255;
    float r  = a0 * inv255;
    float bl = a2 * inv255;
    float I = 0.74f*(r - ya) - 0.27f*(bl - ya);
    float Q = 0.48f*(r - ya) + 0.41f*(bl - ya);

    g_Y[pix]    = Y;
    g_x0[pix]   = colored ? make_float2(I, Q) : make_float2(0.0f, 0.0f);
    g_mask[pix] = colored ? 1 : 0;
}

// ---------------- weights: quantized unorm16 ----------------
__global__ void weights_kernel() {
    int pix = blockIdx.x * blockDim.x + threadIdx.x;
    if (pix >= NPIX) return;
    int i = pix / WW, j = pix % WW;

    const int di[8] = {-1,-1,-1, 0, 0, 1, 1, 1};
    const int dj[8] = {-1, 0, 1,-1, 1,-1, 0, 1};

    float Y = g_Y[pix];
    float nbr[8], valid[8];
    #pragma unroll
    for (int k = 0; k < 8; k++) {
        int ii = i + di[k], jj = j + dj[k];
        bool in = (ii >= 0) & (ii < HH) & (jj >= 0) & (jj < WW);
        valid[k] = in ? 1.0f : 0.0f;
        nbr[k]   = in ? g_Y[ii*WW + jj] : 0.0f;
    }

    float count = 1.0f, s = Y;
    #pragma unroll
    for (int k = 0; k < 8; k++) { count += valid[k]; s += nbr[k] * valid[k]; }
    float mean = s / count;

    float var = (Y - mean) * (Y - mean);
    #pragma unroll
    for (int k = 0; k < 8; k++) {
        float d = nbr[k] - mean;
        var += d * d * valid[k];
    }
    var /= count;
    float vs = fmaxf(0.6f * var, 2e-6f);
    float inv_vs = 1.0f / vs;

    float w[8], wsum = 0.0f;
    #pragma unroll
    for (int k = 0; k < 8; k++) {
        float d = nbr[k] - Y;
        w[k] = expf(-d * d * inv_vs) * valid[k];
        wsum += w[k];
    }
    // colored pixels: all weights 0 (the all-zero pattern encodes "colored")
    float scale = (g_mask[pix] ? 0.0f : 1.0f) / wsum * 65535.0f;

    unsigned int u[8];
    #pragma unroll
    for (int k = 0; k < 8; k++) u[k] = (unsigned int)rintf(w[k] * scale);

    uint4 q;
    q.x = u[0] | (u[1] << 16);
    q.y = u[2] | (u[3] << 16);
    q.z = u[4] | (u[5] << 16);
    q.w = u[6] | (u[7] << 16);
    g_wq[pix] = q;
}

__device__ __forceinline__ void unpack_w(uint4 q, float* w, float& c) {
    const float S = 1.0f / 65535.0f;
    w[0] = (float)(q.x & 0xFFFFu) * S;  w[1] = (float)(q.x >> 16) * S;
    w[2] = (float)(q.y & 0xFFFFu) * S;  w[3] = (float)(q.y >> 16) * S;
    w[4] = (float)(q.z & 0xFFFFu) * S;  w[5] = (float)(q.z >> 16) * S;
    w[6] = (float)(q.w & 0xFFFFu) * S;  w[7] = (float)(q.w >> 16) * S;
    c = ((q.x | q.y | q.z | q.w) == 0u) ? 1.0f : 0.0f;
}

// ---------------- persistent kernel: all 100 iterations + final RGB ----------------
// 256 blocks x 512 threads. Block b owns rows 4b..4b+3. Thread layout: rows of
// 128 threads; thread u in a row handles cols u, u+128, ..., u+896 (8 px).
// Weights live in smem (loaded once); x ping-pongs in global with a software
// grid barrier per iteration. __launch_bounds__(512,2) guarantees >=2 blocks/SM
// => all 256 blocks co-resident => barrier cannot deadlock.
__global__ void __launch_bounds__(NTHR, 2)
persist_kernel(float* __restrict__ out) {
    extern __shared__ uint4 s_wq[];          // [RPB * WW] packed weights

    int tid = threadIdx.x;
    int b   = blockIdx.x;
    int r0  = b * RPB;

    // stage this block's weights into smem (coalesced uint4)
    for (int idx = tid; idx < RPB * WW; idx += NTHR)
        s_wq[idx] = g_wq[r0 * WW + idx];
    __syncthreads();

    int rloc = tid >> 7;                     // 0..3 local row
    int u    = tid & 127;                    // 0..127 column lane
    int i    = r0 + rloc;
    int im   = (i > 0)      ? i - 1 : 0;
    int ip   = (i < HH - 1) ? i + 1 : HH - 1;

    #pragma unroll 1
    for (int it = 0; it < N_ITERS; ++it) {
        const float2* __restrict__ xin  = (it & 1) ? g_x1 : g_x0;
        float2*       __restrict__ xout = (it & 1) ? g_x0 : g_x1;
        const float2* rm = xin + im * WW;
        const float2* rc = xin + i  * WW;
        const float2* rp = xin + ip * WW;

        float2 res[8];
        #pragma unroll
        for (int p = 0; p < 8; p++) {
            int j  = u + p * 128;
            int jm = (j > 0)      ? j - 1 : 0;
            int jp = (j < WW - 1) ? j + 1 : WW - 1;

            uint4 q = s_wq[rloc * WW + j];
            float w[8], c;
            unpack_w(q, w, c);

            float2 ctr = rc[j];
            float ax = c * ctr.x, ay = c * ctr.y;
            float2 t;
            t = rm[jm]; ax = fmaf(w[0], t.x, ax); ay = fmaf(w[0], t.y, ay);
            t = rm[j ]; ax = fmaf(w[1], t.x, ax); ay = fmaf(w[1], t.y, ay);
            t = rm[jp]; ax = fmaf(w[2], t.x, ax); ay = fmaf(w[2], t.y, ay);
            t = rc[jm]; ax = fmaf(w[3], t.x, ax); ay = fmaf(w[3], t.y, ay);
            t = rc[jp]; ax = fmaf(w[4], t.x, ax); ay = fmaf(w[4], t.y, ay);
            t = rp[jm]; ax = fmaf(w[5], t.x, ax); ay = fmaf(w[5], t.y, ay);
            t = rp[j ]; ax = fmaf(w[6], t.x, ax); ay = fmaf(w[6], t.y, ay);
            t = rp[jp]; ax = fmaf(w[7], t.x, ax); ay = fmaf(w[7], t.y, ay);
            res[p] = make_float2(ax, ay);
        }

        if (it == N_ITERS - 1) {
            // final: YIQ -> RGB straight from registers, no x store
            #pragma unroll
            for (int p = 0; p < 8; p++) {
                int j = u + p * 128;
                int pix = i * WW + j;
                float y = g_Y[pix];
                float I = res[p].x, Q = res[p].y;
                float r = y + 0.9468822170900693f  * I + 0.6235565819861433f * Q;
                float g = y - 0.27478764629897834f * I - 0.6356910791873801f * Q;
                float bb = y - 1.1085450346420322f * I + 1.7090069284064666f * Q;
                int o = 3 * pix;
                out[o+0] = fminf(fmaxf(r,  0.0f), 1.0f) * 255.0f;
                out[o+1] = fminf(fmaxf(g,  0.0f), 1.0f) * 255.0f;
                out[o+2] = fminf(fmaxf(bb, 0.0f), 1.0f) * 255.0f;
            }
            break;   // no barrier needed after last iteration
        }

        #pragma unroll
        for (int p = 0; p < 8; p++)
            xout[i * WW + u + p * 128] = res[p];

        // ---- software grid barrier (arrival-count, monotonic phase) ----
        __syncthreads();                 // all block stores issued
        if (tid == 0) {
            __threadfence();             // publish this block's stores (to L2)
            unsigned int a = atomicAdd(&g_bar_count, 1u);
            if (a == (unsigned int)(NBLK * (it + 1)) - 1u) {
                g_bar_phase = (unsigned int)(it + 1);       // release
            } else {
                while (g_bar_phase < (unsigned int)(it + 1)) { }   // spin on L2
            }
        }
        __syncthreads();
        __threadfence();   // CCTL.IVALL: invalidate L1D so next iter reads fresh x
    }
}

extern "C" void kernel_launch(void* const* d_in, const int* in_sizes, int n_in,
                              void* d_out, int out_size) {
    const float* gray = (const float*)d_in[0];
    const float* app  = (const float*)d_in[1];
    float* out = (float*)d_out;

    int threads = 256;
    int blocks1d = (NPIX + threads - 1) / threads;

    setup_kernel<<<blocks1d, threads>>>(gray, app);
    weights_kernel<<<blocks1d, threads>>>();

    static int smem_set = 0;
    if (!smem_set) {
        cudaFuncSetAttribute(persist_kernel,
                             cudaFuncAttributeMaxDynamicSharedMemorySize, SMEM_BYTES);
        smem_set = 1;
    }
    persist_kernel<<<NBLK, NTHR, SMEM_BYTES>>>(out);
}

// round 10
// speedup vs baseline: 1.0458x; 1.0458x over previous
#include <cuda_runtime.h>
#include <math.h>

#define HH 1024
#define WW 1024
#define NPIX (HH * WW)
#define N_ITERS 100

// tile: 32x8 block -> 34x10 halo tile of float2
#define TW 34
#define TH 10

// ---------------- device scratch (statically allocated, ~36 MB) ----------------
__device__ uint4  g_wq[NPIX];       // 8x unorm16 weights per pixel (16B)
__device__ float  g_Y[NPIX];        // luminance plane
__device__ unsigned char g_mask[NPIX];
__device__ float2 g_x0[NPIX];       // ping
__device__ float2 g_x1[NPIX];       // pong

// ---------------- setup ----------------
__global__ void setup_kernel(const float* __restrict__ gray,
                             const float* __restrict__ app) {
    int pix = blockIdx.x * blockDim.x + threadIdx.x;
    if (pix >= NPIX) return;
    float g0 = gray[3*pix+0], g1 = gray[3*pix+1], g2 = gray[3*pix+2];
    float a0 = app [3*pix+0], a1 = app [3*pix+1], a2 = app [3*pix+2];

    const float inv255 = 1.0f / 255.0f;
    float diff = (fabsf(g0-a0) + fabsf(g1-a1) + fabsf(g2-a2)) * inv255;
    bool colored = diff > 0.01f;

    float Y = (0.3f*g0 + 0.59f*g1 + 0.11f*g2) * inv255;

    float ya = (0.3f*a0 + 0.59f*a1 + 0.11f*a2) * inv255;
    float r  = a0 * inv255;
    float bl = a2 * inv255;
    float I = 0.74f*(r - ya) - 0.27f*(bl - ya);
    float Q = 0.48f*(r - ya) + 0.41f*(bl - ya);

    g_Y[pix]    = Y;
    g_x0[pix]   = colored ? make_float2(I, Q) : make_float2(0.0f, 0.0f);
    g_mask[pix] = colored ? 1 : 0;
}

// ---------------- weights: quantized unorm16 ----------------
__global__ void weights_kernel() {
    int pix = blockIdx.x * blockDim.x + threadIdx.x;
    if (pix >= NPIX) return;
    int i = pix / WW, j = pix % WW;

    const int di[8] = {-1,-1,-1, 0, 0, 1, 1, 1};
    const int dj[8] = {-1, 0, 1,-1, 1,-1, 0, 1};

    float Y = g_Y[pix];
    float nbr[8], valid[8];
    #pragma unroll
    for (int k = 0; k < 8; k++) {
        int ii = i + di[k], jj = j + dj[k];
        bool in = (ii >= 0) & (ii < HH) & (jj >= 0) & (jj < WW);
        valid[k] = in ? 1.0f : 0.0f;
        nbr[k]   = in ? g_Y[ii*WW + jj] : 0.0f;
    }

    float count = 1.0f, s = Y;
    #pragma unroll
    for (int k = 0; k < 8; k++) { count += valid[k]; s += nbr[k] * valid[k]; }
    float mean = s / count;

    float var = (Y - mean) * (Y - mean);
    #pragma unroll
    for (int k = 0; k < 8; k++) {
        float d = nbr[k] - mean;
        var += d * d * valid[k];
    }
    var /= count;
    float vs = fmaxf(0.6f * var, 2e-6f);
    float inv_vs = 1.0f / vs;

    float w[8], wsum = 0.0f;
    #pragma unroll
    for (int k = 0; k < 8; k++) {
        float d = nbr[k] - Y;
        w[k] = expf(-d * d * inv_vs) * valid[k];
        wsum += w[k];
    }
    // colored pixels: all weights 0 (the all-zero pattern encodes "colored")
    float scale = (g_mask[pix] ? 0.0f : 1.0f) / wsum * 65535.0f;

    unsigned int u[8];
    #pragma unroll
    for (int k = 0; k < 8; k++) u[k] = (unsigned int)rintf(w[k] * scale);

    uint4 q;
    q.x = u[0] | (u[1] << 16);
    q.y = u[2] | (u[3] << 16);
    q.z = u[4] | (u[5] << 16);
    q.w = u[6] | (u[7] << 16);
    g_wq[pix] = q;
}

__device__ __forceinline__ void unpack_w(uint4 q, float* w, float& c) {
    const float S = 1.0f / 65535.0f;
    w[0] = (float)(q.x & 0xFFFFu) * S;  w[1] = (float)(q.x >> 16) * S;
    w[2] = (float)(q.y & 0xFFFFu) * S;  w[3] = (float)(q.y >> 16) * S;
    w[4] = (float)(q.z & 0xFFFFu) * S;  w[5] = (float)(q.z >> 16) * S;
    w[6] = (float)(q.w & 0xFFFFu) * S;  w[7] = (float)(q.w >> 16) * S;
    c = ((q.x | q.y | q.z | q.w) == 0u) ? 1.0f : 0.0f;
}

// shared-tile stencil body: computes this thread's new (I,Q) value
__device__ __forceinline__ float2 stencil_body(const float2* __restrict__ xin,
                                               float2 (*sx)[TW],
                                               int i, int j, int bi0, int bj0,
                                               int tid) {
    // ---- cooperative tile load: 34x10, clamped (garbage slots have weight 0)
    for (int idx = tid; idx < TW * TH; idx += 256) {
        int r = idx / TW, c = idx % TW;
        int gi = min(max(bi0 - 1 + r, 0), HH - 1);
        int gj = min(max(bj0 - 1 + c, 0), WW - 1);
        sx[r][c] = __ldg(&xin[gi * WW + gj]);
    }

    uint4 q = g_wq[i * WW + j];        // overlaps with the tile load latency
    __syncthreads();

    float w[8], c;
    unpack_w(q, w, c);

    int ty = threadIdx.y, tx = threadIdx.x;   // tile coords: row ty+1, col tx+1
    float2 ctr = sx[ty+1][tx+1];
    float ax = c * ctr.x, ay = c * ctr.y;
    float2 t;
    t = sx[ty  ][tx  ]; ax = fmaf(w[0], t.x, ax); ay = fmaf(w[0], t.y, ay);
    t = sx[ty  ][tx+1]; ax = fmaf(w[1], t.x, ax); ay = fmaf(w[1], t.y, ay);
    t = sx[ty  ][tx+2]; ax = fmaf(w[2], t.x, ax); ay = fmaf(w[2], t.y, ay);
    t = sx[ty+1][tx  ]; ax = fmaf(w[3], t.x, ax); ay = fmaf(w[3], t.y, ay);
    t = sx[ty+1][tx+2]; ax = fmaf(w[4], t.x, ax); ay = fmaf(w[4], t.y, ay);
    t = sx[ty+2][tx  ]; ax = fmaf(w[5], t.x, ax); ay = fmaf(w[5], t.y, ay);
    t = sx[ty+2][tx+1]; ax = fmaf(w[6], t.x, ax); ay = fmaf(w[6], t.y, ay);
    t = sx[ty+2][tx+2]; ax = fmaf(w[7], t.x, ax); ay = fmaf(w[7], t.y, ay);
    return make_float2(ax, ay);
}

// ---------------- main stencil iteration (smem tile, 1 px/thread) ----------------
__global__ void __launch_bounds__(256)
iter_kernel(int src_is_x0) {
    __shared__ float2 sx[TH][TW];
    int tx = threadIdx.x, ty = threadIdx.y;
    int tid = ty * 32 + tx;
    int bj0 = blockIdx.x * 32;
    int bi0 = blockIdx.y * 8;
    int j = bj0 + tx, i = bi0 + ty;

    const float2* __restrict__ xin  = src_is_x0 ? g_x0 : g_x1;
    float2*       __restrict__ xout = src_is_x0 ? g_x1 : g_x0;

    float2 r = stencil_body(xin, sx, i, j, bi0, bj0, tid);
    xout[i * WW + j] = r;
}

// ---------------- fused last step + YIQ->RGB ----------------
__global__ void __launch_bounds__(256)
iter_final_kernel(float* __restrict__ out, int src_is_x0) {
    __shared__ float2 sx[TH][TW];
    int tx = threadIdx.x, ty = threadIdx.y;
    int tid = ty * 32 + tx;
    int bj0 = blockIdx.x * 32;
    int bi0 = blockIdx.y * 8;
    int j = bj0 + tx, i = bi0 + ty;

    const float2* __restrict__ xin = src_is_x0 ? g_x0 : g_x1;

    float2 v = stencil_body(xin, sx, i, j, bi0, bj0, tid);

    int pix = i * WW + j;
    float y = g_Y[pix];
    float I = v.x, Q = v.y;
    float r = y + 0.9468822170900693f  * I + 0.6235565819861433f * Q;
    float g = y - 0.27478764629897834f * I - 0.6356910791873801f * Q;
    float b = y - 1.1085450346420322f  * I + 1.7090069284064666f * Q;
    int o = 3 * pix;
    out[o+0] = fminf(fmaxf(r, 0.0f), 1.0f) * 255.0f;
    out[o+1] = fminf(fmaxf(g, 0.0f), 1.0f) * 255.0f;
    out[o+2] = fminf(fmaxf(b, 0.0f), 1.0f) * 255.0f;
}

extern "C" void kernel_launch(void* const* d_in, const int* in_sizes, int n_in,
                              void* d_out, int out_size) {
    const float* gray = (const float*)d_in[0];
    const float* app  = (const float*)d_in[1];
    float* out = (float*)d_out;

    int threads = 256;
    int blocks1d = (NPIX + threads - 1) / threads;

    setup_kernel<<<blocks1d, threads>>>(gray, app);
    weights_kernel<<<blocks1d, threads>>>();

    dim3 blk(32, 8);
    dim3 grd(WW / 32, HH / 8);
    int src_is_x0 = 1;
    for (int it = 0; it < N_ITERS - 1; it++) {   // 99 normal steps
        iter_kernel<<<grd, blk>>>(src_is_x0);
        src_is_x0 ^= 1;
    }
    // step 100 fused with RGB conversion (after 99 steps field is in g_x1, src_is_x0==0)
    iter_final_kernel<<<grd, blk>>>(out, src_is_x0);
}

// round 12
// speedup vs baseline: 1.4199x; 1.3577x over previous
#include <cuda_runtime.h>
#include <math.h>

#define HH 1024
#define WW 1024
#define NPIX (HH * WW)
#define N_ITERS 100

// ---------------- device scratch (statically allocated, ~36 MB) ----------------
__device__ uint4  g_wq[NPIX];       // 8x unorm16 weights per pixel (16B)
__device__ float  g_Y[NPIX];        // luminance plane
__device__ float2 g_x0[NPIX];       // ping
__device__ float2 g_x1[NPIX];       // pong

__device__ __forceinline__ float luma(float r, float g, float b) {
    return (0.3f * r + 0.59f * g + 0.11f * b) * (1.0f / 255.0f);
}

// ---------------- prep: setup + weights fused (one pass) ----------------
// Computes per-pixel: Y, initial x0 (= b), and the 8 quantized weights.
// Neighbor Y values are recomputed from gray directly (identical float
// expression as the center Y, so results are bitwise identical to the
// two-pass version).
__global__ void prep_kernel(const float* __restrict__ gray,
                            const float* __restrict__ app) {
    int pix = blockIdx.x * blockDim.x + threadIdx.x;
    if (pix >= NPIX) return;
    int i = pix / WW, j = pix % WW;

    // ---- own pixel ----
    float g0 = gray[3*pix+0], g1 = gray[3*pix+1], g2 = gray[3*pix+2];
    float a0 = app [3*pix+0], a1 = app [3*pix+1], a2 = app [3*pix+2];

    const float inv255 = 1.0f / 255.0f;
    float diff = (fabsf(g0-a0) + fabsf(g1-a1) + fabsf(g2-a2)) * inv255;
    bool colored = diff > 0.01f;

    float Y = luma(g0, g1, g2);

    float ya = luma(a0, a1, a2);
    float r  = a0 * inv255;
    float bl = a2 * inv255;
    float I = 0.74f*(r - ya) - 0.27f*(bl - ya);
    float Q = 0.48f*(r - ya) + 0.41f*(bl - ya);

    g_Y[pix]  = Y;
    g_x0[pix] = colored ? make_float2(I, Q) : make_float2(0.0f, 0.0f);

    // ---- neighbor Y from gray (recomputed; bitwise same as g_Y would be) ----
    const int di[8] = {-1,-1,-1, 0, 0, 1, 1, 1};
    const int dj[8] = {-1, 0, 1,-1, 1,-1, 0, 1};

    float nbr[8], valid[8];
    #pragma unroll
    for (int k = 0; k < 8; k++) {
        int ii = i + di[k], jj = j + dj[k];
        bool in = (ii >= 0) & (ii < HH) & (jj >= 0) & (jj < WW);
        valid[k] = in ? 1.0f : 0.0f;
        if (in) {
            int np = (ii * WW + jj) * 3;
            nbr[k] = luma(gray[np], gray[np+1], gray[np+2]);
        } else {
            nbr[k] = 0.0f;
        }
    }

    float count = 1.0f, s = Y;
    #pragma unroll
    for (int k = 0; k < 8; k++) { count += valid[k]; s += nbr[k] * valid[k]; }
    float mean = s / count;

    float var = (Y - mean) * (Y - mean);
    #pragma unroll
    for (int k = 0; k < 8; k++) {
        float d = nbr[k] - mean;
        var += d * d * valid[k];
    }
    var /= count;
    float vs = fmaxf(0.6f * var, 2e-6f);
    float inv_vs = 1.0f / vs;

    float w[8], wsum = 0.0f;
    #pragma unroll
    for (int k = 0; k < 8; k++) {
        float d = nbr[k] - Y;
        w[k] = expf(-d * d * inv_vs) * valid[k];
        wsum += w[k];
    }
    // colored pixels: all weights 0 (the all-zero pattern encodes "colored")
    float scale = (colored ? 0.0f : 1.0f) / wsum * 65535.0f;

    unsigned int u[8];
    #pragma unroll
    for (int k = 0; k < 8; k++) u[k] = (unsigned int)rintf(w[k] * scale);

    uint4 q;
    q.x = u[0] | (u[1] << 16);
    q.y = u[2] | (u[3] << 16);
    q.z = u[4] | (u[5] << 16);
    q.w = u[6] | (u[7] << 16);
    g_wq[pix] = q;
}

__device__ __forceinline__ void unpack_w(uint4 q, float* w, float& c) {
    const float S = 1.0f / 65535.0f;
    w[0] = (float)(q.x & 0xFFFFu) * S;  w[1] = (float)(q.x >> 16) * S;
    w[2] = (float)(q.y & 0xFFFFu) * S;  w[3] = (float)(q.y >> 16) * S;
    w[4] = (float)(q.z & 0xFFFFu) * S;  w[5] = (float)(q.z >> 16) * S;
    w[6] = (float)(q.w & 0xFFFFu) * S;  w[7] = (float)(q.w >> 16) * S;
    c = ((q.x | q.y | q.z | q.w) == 0u) ? 1.0f : 0.0f;
}

// stencil body for pixel (i,j): identical per-thread work to the proven R7 kernel
__device__ __forceinline__ float2 stencil_px(const float2* __restrict__ xin,
                                             int i, int j, int pix) {
    int im = (i > 0)      ? i - 1 : 0;
    int ip = (i < HH - 1) ? i + 1 : HH - 1;
    int jm = (j > 0)      ? j - 1 : 0;
    int jp = (j < WW - 1) ? j + 1 : WW - 1;

    const float2* rm = xin + im * WW;
    const float2* r0 = xin + i  * WW;
    const float2* rp = xin + ip * WW;

    uint4 q = g_wq[pix];
    float w[8], c;
    unpack_w(q, w, c);

    float2 ctr = r0[j];
    float ax = c * ctr.x, ay = c * ctr.y;
    float2 t;
    t = rm[jm]; ax = fmaf(w[0], t.x, ax); ay = fmaf(w[0], t.y, ay);
    t = rm[j ]; ax = fmaf(w[1], t.x, ax); ay = fmaf(w[1], t.y, ay);
    t = rm[jp]; ax = fmaf(w[2], t.x, ax); ay = fmaf(w[2], t.y, ay);
    t = r0[jm]; ax = fmaf(w[3], t.x, ax); ay = fmaf(w[3], t.y, ay);
    t = r0[jp]; ax = fmaf(w[4], t.x, ax); ay = fmaf(w[4], t.y, ay);
    t = rp[jm]; ax = fmaf(w[5], t.x, ax); ay = fmaf(w[5], t.y, ay);
    t = rp[j ]; ax = fmaf(w[6], t.x, ax); ay = fmaf(w[6], t.y, ay);
    t = rp[jp]; ax = fmaf(w[7], t.x, ax); ay = fmaf(w[7], t.y, ay);
    return make_float2(ax, ay);
}

// ---------------- main stencil iteration, direction specialized ----------------
template <bool SRC_IS_X0>
__global__ void __launch_bounds__(256)
iter_kernel_t() {
    int j = blockIdx.x * 32 + threadIdx.x;
    int i = blockIdx.y * 8  + threadIdx.y;
    int pix = i * WW + j;

    const float2* __restrict__ xin  = SRC_IS_X0 ? g_x0 : g_x1;
    float2*       __restrict__ xout = SRC_IS_X0 ? g_x1 : g_x0;

    xout[pix] = stencil_px(xin, i, j, pix);
}

// ---------------- fused last step + YIQ->RGB (reads g_x1: step 100 src) ----------
__global__ void __launch_bounds__(256)
iter_final_kernel(float* __restrict__ out) {
    int j = blockIdx.x * 32 + threadIdx.x;
    int i = blockIdx.y * 8  + threadIdx.y;
    int pix = i * WW + j;

    float2 v = stencil_px(g_x1, i, j, pix);

    float y = g_Y[pix];
    float I = v.x, Q = v.y;
    float r = y + 0.9468822170900693f  * I + 0.6235565819861433f * Q;
    float g = y - 0.27478764629897834f * I - 0.6356910791873801f * Q;
    float b = y - 1.1085450346420322f  * I + 1.7090069284064666f * Q;
    int o = 3 * pix;
    out[o+0] = fminf(fmaxf(r, 0.0f), 1.0f) * 255.0f;
    out[o+1] = fminf(fmaxf(g, 0.0f), 1.0f) * 255.0f;
    out[o+2] = fminf(fmaxf(b, 0.0f), 1.0f) * 255.0f;
}

extern "C" void kernel_launch(void* const* d_in, const int* in_sizes, int n_in,
                              void* d_out, int out_size) {
    const float* gray = (const float*)d_in[0];
    const float* app  = (const float*)d_in[1];
    float* out = (float*)d_out;

    int threads = 256;
    int blocks1d = (NPIX + threads - 1) / threads;

    prep_kernel<<<blocks1d, threads>>>(gray, app);

    dim3 blk(32, 8);
    dim3 grd(WW / 32, HH / 8);
    // 99 normal steps: it=0 reads x0 (even it -> src x0), alternating
    for (int it = 0; it < N_ITERS - 1; it++) {
        if ((it & 1) == 0) iter_kernel_t<true ><<<grd, blk>>>();
        else               iter_kernel_t<false><<<grd, blk>>>();
    }
    // it=98 (even) wrote g_x1; step 100 reads g_x1, fused with RGB conversion
    iter_final_kernel<<<grd, blk>>>(out);
}